// round 1
// baseline (speedup 1.0000x reference)
#include <cuda_runtime.h>
#include <math.h>

#define Bsz 64
#define Cdim 2048
#define HWs 288
#define NCH 8
#define CCH (Cdim / NCH)   // 256

// Scratch (no allocation allowed; __device__ globals)
__device__ float g_An[2 * Cdim];                    // normalized anchors
__device__ float g_part[Bsz * HWs * NCH * 3];       // per-(b,t,chunk) partial s2/d0/d1
__device__ float g_invden[Bsz * 2];                 // 1/(sum m + 1e-6)

// ---------------------------------------------------------------------------
// Kernel 0: normalize anchors (2 rows of 2048)
// ---------------------------------------------------------------------------
__global__ void k_anchors(const float* __restrict__ anchors) {
    __shared__ float red[8];
    __shared__ float s_inv;
    int tid = threadIdx.x;  // 256
    for (int k = 0; k < 2; ++k) {
        float s = 0.f;
        for (int c = tid; c < Cdim; c += 256) {
            float v = anchors[k * Cdim + c];
            s += v * v;
        }
        #pragma unroll
        for (int o = 16; o; o >>= 1) s += __shfl_down_sync(0xffffffffu, s, o);
        if ((tid & 31) == 0) red[tid >> 5] = s;
        __syncthreads();
        if (tid < 32) {
            float q = (tid < 8) ? red[tid] : 0.f;
            #pragma unroll
            for (int o = 4; o; o >>= 1) q += __shfl_down_sync(0xffffffffu, q, o);
            if (tid == 0) s_inv = 1.f / fmaxf(sqrtf(q), 1e-12f);
        }
        __syncthreads();
        float inv = s_inv;
        for (int c = tid; c < Cdim; c += 256)
            g_An[k * Cdim + c] = anchors[k * Cdim + c] * inv;
        __syncthreads();
    }
}

// ---------------------------------------------------------------------------
// Kernel 1: per-token ||x||^2 and dots with normalized anchors (pass 1 over x)
// grid = (B, NCH), block = 288 (one thread per token)
// ---------------------------------------------------------------------------
__global__ void k_dots(const float* __restrict__ x) {
    int b  = blockIdx.x;
    int ch = blockIdx.y;
    int t  = threadIdx.x;  // 0..287

    __shared__ float a0s[CCH], a1s[CCH];
    if (t < CCH) {
        a0s[t] = g_An[ch * CCH + t];
        a1s[t] = g_An[Cdim + ch * CCH + t];
    }
    __syncthreads();

    const float* xp = x + ((size_t)b * Cdim + (size_t)ch * CCH) * HWs + t;
    float s2 = 0.f, d0 = 0.f, d1 = 0.f;
    #pragma unroll 8
    for (int i = 0; i < CCH; ++i) {
        float v = xp[(size_t)i * HWs];
        s2 = fmaf(v, v, s2);
        d0 = fmaf(v, a0s[i], d0);
        d1 = fmaf(v, a1s[i], d1);
    }
    float* p = g_part + (((size_t)b * HWs + t) * NCH + ch) * 3;
    p[0] = s2; p[1] = d0; p[2] = d1;
}

// ---------------------------------------------------------------------------
// Kernel 2: reduce partials, build K, 7 sinkhorn iterations, emit m and invden
// grid = B, block = 288 (one thread per token)
// ---------------------------------------------------------------------------
__global__ void k_sinkhorn(float* __restrict__ out_m) {
    int b = blockIdx.x;
    int t = threadIdx.x;  // 0..287

    const float* p = g_part + ((size_t)b * HWs + t) * NCH * 3;
    float s2 = 0.f, d0 = 0.f, d1 = 0.f;
    #pragma unroll
    for (int ch = 0; ch < NCH; ++ch) {
        s2 += p[ch * 3 + 0];
        d0 += p[ch * 3 + 1];
        d1 += p[ch * 3 + 2];
    }
    float inorm = 1.f / fmaxf(sqrtf(s2), 1e-12f);
    const float ieps = 1.f / 0.07f;
    float K0 = expf(-(1.f - d0 * inorm) * ieps) + 1e-8f;
    float K1 = expf(-(1.f - d1 * inorm) * ieps) + 1e-8f;

    __shared__ float red0[16], red1[16];
    __shared__ float bc0, bc1;

    float v0 = 1.f, v1 = 1.f, u = 0.f;
    const float a = 1.f / (float)HWs;

    for (int it = 0; it < 7; ++it) {
        float Kv = K0 * v0 + K1 * v1 + 1e-8f;
        u = a / Kv;
        float r0 = K0 * u, r1 = K1 * u;
        #pragma unroll
        for (int o = 16; o; o >>= 1) {
            r0 += __shfl_down_sync(0xffffffffu, r0, o);
            r1 += __shfl_down_sync(0xffffffffu, r1, o);
        }
        if ((t & 31) == 0) { red0[t >> 5] = r0; red1[t >> 5] = r1; }
        __syncthreads();
        if (t < 32) {
            float q0 = (t < 9) ? red0[t] : 0.f;
            float q1 = (t < 9) ? red1[t] : 0.f;
            #pragma unroll
            for (int o = 8; o; o >>= 1) {
                q0 += __shfl_down_sync(0xffffffffu, q0, o);
                q1 += __shfl_down_sync(0xffffffffu, q1, o);
            }
            if (t == 0) { bc0 = 0.5f / (q0 + 1e-8f); bc1 = 0.5f / (q1 + 1e-8f); }
        }
        __syncthreads();
        v0 = bc0; v1 = bc1;
        __syncthreads();
    }

    float m0 = K0 * u * v0 * (float)HWs;
    float m1 = K1 * u * v1 * (float)HWs;
    float* om = out_m + (size_t)b * 2 * HWs;
    om[t]       = m0;
    om[HWs + t] = m1;

    // den reduction
    float r0 = m0, r1 = m1;
    #pragma unroll
    for (int o = 16; o; o >>= 1) {
        r0 += __shfl_down_sync(0xffffffffu, r0, o);
        r1 += __shfl_down_sync(0xffffffffu, r1, o);
    }
    if ((t & 31) == 0) { red0[t >> 5] = r0; red1[t >> 5] = r1; }
    __syncthreads();
    if (t < 32) {
        float q0 = (t < 9) ? red0[t] : 0.f;
        float q1 = (t < 9) ? red1[t] : 0.f;
        #pragma unroll
        for (int o = 8; o; o >>= 1) {
            q0 += __shfl_down_sync(0xffffffffu, q0, o);
            q1 += __shfl_down_sync(0xffffffffu, q1, o);
        }
        if (t == 0) {
            g_invden[b * 2 + 0] = 1.f / (q0 + 1e-6f);
            g_invden[b * 2 + 1] = 1.f / (q1 + 1e-6f);
        }
    }
}

// ---------------------------------------------------------------------------
// Kernel 3: masked pooling (pass 2 over x).
// grid = (C/8, B), block = 256 (8 warps; warp w handles channel c = 8*bx + w)
// ---------------------------------------------------------------------------
__global__ void k_pool(const float* __restrict__ x,
                       const float* __restrict__ m,
                       float* __restrict__ out) {
    int b  = blockIdx.y;
    int cg = blockIdx.x;
    int tid = threadIdx.x;

    __shared__ float ms[2 * HWs];
    __shared__ float inv[2];
    for (int i = tid; i < 2 * HWs; i += 256) ms[i] = m[(size_t)b * 2 * HWs + i];
    if (tid < 2) inv[tid] = g_invden[b * 2 + tid];
    __syncthreads();

    int w = tid >> 5, lane = tid & 31;
    int c = cg * 8 + w;
    const float* xp = x + ((size_t)b * Cdim + c) * HWs;

    float s0 = 0.f, s1 = 0.f;
    #pragma unroll
    for (int j = 0; j < 9; ++j) {
        int idx = lane + 32 * j;
        float v = xp[idx];
        s0 = fmaf(v, ms[idx], s0);
        s1 = fmaf(v, ms[HWs + idx], s1);
    }
    #pragma unroll
    for (int o = 16; o; o >>= 1) {
        s0 += __shfl_down_sync(0xffffffffu, s0, o);
        s1 += __shfl_down_sync(0xffffffffu, s1, o);
    }
    if (lane == 0) {
        out[(size_t)b * Cdim + c]                     = s0 * inv[0];
        out[(size_t)Bsz * Cdim + (size_t)b * Cdim + c] = s1 * inv[1];
    }
}

// ---------------------------------------------------------------------------
extern "C" void kernel_launch(void* const* d_in, const int* in_sizes, int n_in,
                              void* d_out, int out_size) {
    const float* x       = (const float*)d_in[0];  // (64, 2048, 24, 12)
    const float* anchors = (const float*)d_in[1];  // (2, 2048)
    float* out = (float*)d_out;
    // layout: [c0 (B*C)] [c1 (B*C)] [m (B*2*HW)]
    float* out_m = out + (size_t)2 * Bsz * Cdim;

    k_anchors<<<1, 256>>>(anchors);
    k_dots<<<dim3(Bsz, NCH), HWs>>>(x);
    k_sinkhorn<<<Bsz, HWs>>>(out_m);
    k_pool<<<dim3(Cdim / 8, Bsz), 256>>>(x, out_m, out);
}

// round 2
// speedup vs baseline: 1.2098x; 1.2098x over previous
#include <cuda_runtime.h>
#include <math.h>

#define Bsz 64
#define Cdim 2048
#define HWs 288
#define NCH 8
#define CCH (Cdim / NCH)   // 256

// Scratch (no allocation allowed; __device__ globals)
__device__ float g_An[2 * Cdim];                    // normalized anchors
__device__ float g_part[Bsz * NCH * 3 * HWs];       // partials, layout (b,ch,j,t)
__device__ float g_invden[Bsz * 2];                 // 1/(sum m + 1e-6)

// ---------------------------------------------------------------------------
// Kernel 0: normalize anchors (2 rows of 2048)
// ---------------------------------------------------------------------------
__global__ void k_anchors(const float* __restrict__ anchors) {
    __shared__ float red[8];
    __shared__ float s_inv;
    int tid = threadIdx.x;  // 256
    for (int k = 0; k < 2; ++k) {
        float s = 0.f;
        for (int c = tid; c < Cdim; c += 256) {
            float v = anchors[k * Cdim + c];
            s += v * v;
        }
        #pragma unroll
        for (int o = 16; o; o >>= 1) s += __shfl_down_sync(0xffffffffu, s, o);
        if ((tid & 31) == 0) red[tid >> 5] = s;
        __syncthreads();
        if (tid < 32) {
            float q = (tid < 8) ? red[tid] : 0.f;
            #pragma unroll
            for (int o = 4; o; o >>= 1) q += __shfl_down_sync(0xffffffffu, q, o);
            if (tid == 0) s_inv = 1.f / fmaxf(sqrtf(q), 1e-12f);
        }
        __syncthreads();
        float inv = s_inv;
        for (int c = tid; c < Cdim; c += 256)
            g_An[k * Cdim + c] = anchors[k * Cdim + c] * inv;
        __syncthreads();
    }
}

// ---------------------------------------------------------------------------
// Kernel 1: per-token ||x||^2 + anchor dots (pass 1 over x), float4 loads.
// grid = (B, NCH), block = 288.  Thread layout: r4 = t/72 (row group 0..3),
// q = t%72 (quad column). Loop over 64 row-quads; each iter one LDG.128.
// ---------------------------------------------------------------------------
__global__ void k_dots(const float* __restrict__ x) {
    int b  = blockIdx.x;
    int ch = blockIdx.y;
    int t  = threadIdx.x;  // 0..287
    int r4 = t / 72;
    int q  = t % 72;

    __shared__ float a0s[CCH], a1s[CCH];
    if (t < CCH) {
        a0s[t] = g_An[ch * CCH + t];
        a1s[t] = g_An[Cdim + ch * CCH + t];
    }
    __syncthreads();

    const float4* xp = (const float4*)(x + ((size_t)b * Cdim + (size_t)ch * CCH) * HWs);
    // xp is rows of 72 float4

    float s2[4] = {0,0,0,0}, d0[4] = {0,0,0,0}, d1[4] = {0,0,0,0};
    #pragma unroll 4
    for (int i = 0; i < 64; ++i) {
        int row = i * 4 + r4;
        float4 v = xp[(size_t)row * 72 + q];
        float a0 = a0s[row], a1 = a1s[row];
        s2[0] = fmaf(v.x, v.x, s2[0]); d0[0] = fmaf(v.x, a0, d0[0]); d1[0] = fmaf(v.x, a1, d1[0]);
        s2[1] = fmaf(v.y, v.y, s2[1]); d0[1] = fmaf(v.y, a0, d0[1]); d1[1] = fmaf(v.y, a1, d1[1]);
        s2[2] = fmaf(v.z, v.z, s2[2]); d0[2] = fmaf(v.z, a0, d0[2]); d1[2] = fmaf(v.z, a1, d1[2]);
        s2[3] = fmaf(v.w, v.w, s2[3]); d0[3] = fmaf(v.w, a0, d0[3]); d1[3] = fmaf(v.w, a1, d1[3]);
    }

    // Reduce across the 4 row groups via smem.
    __shared__ float rs[4][72][12];
    float* dst = rs[r4][q];
    #pragma unroll
    for (int l = 0; l < 4; ++l) { dst[l] = s2[l]; dst[4+l] = d0[l]; dst[8+l] = d1[l]; }
    __syncthreads();

    if (r4 == 0) {
        float acc[12];
        #pragma unroll
        for (int j = 0; j < 12; ++j)
            acc[j] = rs[0][q][j] + rs[1][q][j] + rs[2][q][j] + rs[3][q][j];
        float* gp = g_part + (((size_t)b * NCH + ch) * 3) * HWs;
        #pragma unroll
        for (int j = 0; j < 3; ++j) {
            float4 o = make_float4(acc[4*j+0], acc[4*j+1], acc[4*j+2], acc[4*j+3]);
            *(float4*)(gp + (size_t)j * HWs + q * 4) = o;
        }
    }
}

// ---------------------------------------------------------------------------
// Kernel 2: reduce partials, build K, 7 sinkhorn iterations, emit m and invden
// grid = B, block = 288 (one thread per token)
// ---------------------------------------------------------------------------
__global__ void k_sinkhorn(float* __restrict__ out_m) {
    int b = blockIdx.x;
    int t = threadIdx.x;  // 0..287

    float s2 = 0.f, d0 = 0.f, d1 = 0.f;
    #pragma unroll
    for (int ch = 0; ch < NCH; ++ch) {
        const float* p = g_part + (((size_t)b * NCH + ch) * 3) * HWs;
        s2 += p[t];
        d0 += p[HWs + t];
        d1 += p[2 * HWs + t];
    }
    float inorm = 1.f / fmaxf(sqrtf(s2), 1e-12f);
    const float ieps = 1.f / 0.07f;
    float K0 = expf(-(1.f - d0 * inorm) * ieps) + 1e-8f;
    float K1 = expf(-(1.f - d1 * inorm) * ieps) + 1e-8f;

    __shared__ float red0[16], red1[16];
    __shared__ float bc0, bc1;

    float v0 = 1.f, v1 = 1.f, u = 0.f;
    const float a = 1.f / (float)HWs;

    for (int it = 0; it < 7; ++it) {
        float Kv = K0 * v0 + K1 * v1 + 1e-8f;
        u = a / Kv;
        float r0 = K0 * u, r1 = K1 * u;
        #pragma unroll
        for (int o = 16; o; o >>= 1) {
            r0 += __shfl_down_sync(0xffffffffu, r0, o);
            r1 += __shfl_down_sync(0xffffffffu, r1, o);
        }
        if ((t & 31) == 0) { red0[t >> 5] = r0; red1[t >> 5] = r1; }
        __syncthreads();
        if (t < 32) {
            float q0 = (t < 9) ? red0[t] : 0.f;
            float q1 = (t < 9) ? red1[t] : 0.f;
            #pragma unroll
            for (int o = 8; o; o >>= 1) {
                q0 += __shfl_down_sync(0xffffffffu, q0, o);
                q1 += __shfl_down_sync(0xffffffffu, q1, o);
            }
            if (t == 0) { bc0 = 0.5f / (q0 + 1e-8f); bc1 = 0.5f / (q1 + 1e-8f); }
        }
        __syncthreads();
        v0 = bc0; v1 = bc1;
        __syncthreads();
    }

    float m0 = K0 * u * v0 * (float)HWs;
    float m1 = K1 * u * v1 * (float)HWs;
    float* om = out_m + (size_t)b * 2 * HWs;
    om[t]       = m0;
    om[HWs + t] = m1;

    // den reduction
    float r0 = m0, r1 = m1;
    #pragma unroll
    for (int o = 16; o; o >>= 1) {
        r0 += __shfl_down_sync(0xffffffffu, r0, o);
        r1 += __shfl_down_sync(0xffffffffu, r1, o);
    }
    if ((t & 31) == 0) { red0[t >> 5] = r0; red1[t >> 5] = r1; }
    __syncthreads();
    if (t < 32) {
        float q0 = (t < 9) ? red0[t] : 0.f;
        float q1 = (t < 9) ? red1[t] : 0.f;
        #pragma unroll
        for (int o = 8; o; o >>= 1) {
            q0 += __shfl_down_sync(0xffffffffu, q0, o);
            q1 += __shfl_down_sync(0xffffffffu, q1, o);
        }
        if (t == 0) {
            g_invden[b * 2 + 0] = 1.f / (q0 + 1e-6f);
            g_invden[b * 2 + 1] = 1.f / (q1 + 1e-6f);
        }
    }
}

// ---------------------------------------------------------------------------
// Kernel 3: masked pooling (pass 2 over x), float4 loads.
// grid = (C/64, B), block = 512.  8 threads per channel, 9 float4 each
// (8 threads x 16B = one 128B line per load instruction).
// ---------------------------------------------------------------------------
__global__ void k_pool(const float* __restrict__ x,
                       const float* __restrict__ m,
                       float* __restrict__ out) {
    int b  = blockIdx.y;
    int cg = blockIdx.x;
    int tid = threadIdx.x;  // 0..511

    __shared__ float ms[2 * HWs];
    __shared__ float inv[2];
    for (int i = tid; i < 2 * HWs; i += 512) ms[i] = m[(size_t)b * 2 * HWs + i];
    if (tid < 2) inv[tid] = g_invden[b * 2 + tid];
    __syncthreads();

    int g = tid >> 3;        // channel within block (0..63)
    int q = tid & 7;         // quad slot (0..7)
    int c = cg * 64 + g;
    const float4* xp = (const float4*)(x + ((size_t)b * Cdim + c) * HWs);
    const float4* m0 = (const float4*)ms;
    const float4* m1 = (const float4*)(ms + HWs);

    float s0 = 0.f, s1 = 0.f;
    #pragma unroll
    for (int j = 0; j < 9; ++j) {
        int i4 = q + 8 * j;
        float4 v  = xp[i4];
        float4 w0 = m0[i4];
        float4 w1 = m1[i4];
        s0 = fmaf(v.x, w0.x, s0); s1 = fmaf(v.x, w1.x, s1);
        s0 = fmaf(v.y, w0.y, s0); s1 = fmaf(v.y, w1.y, s1);
        s0 = fmaf(v.z, w0.z, s0); s1 = fmaf(v.z, w1.z, s1);
        s0 = fmaf(v.w, w0.w, s0); s1 = fmaf(v.w, w1.w, s1);
    }
    #pragma unroll
    for (int o = 4; o; o >>= 1) {
        s0 += __shfl_down_sync(0xffffffffu, s0, o, 8);
        s1 += __shfl_down_sync(0xffffffffu, s1, o, 8);
    }
    if (q == 0) {
        out[(size_t)b * Cdim + c]                      = s0 * inv[0];
        out[(size_t)Bsz * Cdim + (size_t)b * Cdim + c] = s1 * inv[1];
    }
}

// ---------------------------------------------------------------------------
extern "C" void kernel_launch(void* const* d_in, const int* in_sizes, int n_in,
                              void* d_out, int out_size) {
    const float* x       = (const float*)d_in[0];  // (64, 2048, 24, 12)
    const float* anchors = (const float*)d_in[1];  // (2, 2048)
    float* out = (float*)d_out;
    // layout: [c0 (B*C)] [c1 (B*C)] [m (B*2*HW)]
    float* out_m = out + (size_t)2 * Bsz * Cdim;

    k_anchors<<<1, 256>>>(anchors);
    k_dots<<<dim3(Bsz, NCH), HWs>>>(x);
    k_sinkhorn<<<Bsz, HWs>>>(out_m);
    k_pool<<<dim3(Cdim / 64, Bsz), 512>>>(x, out_m, out);
}